// round 1
// baseline (speedup 1.0000x reference)
#include <cuda_runtime.h>

// NSLayer: out = X + (w0*A + w1*A^2 + ... + w6*A^7 + w7*I) @ X,  A = I - X X^T
// 262144 independent 8x8 fp32 matrices. One thread per matrix, fully
// register-resident; smem staging (stride-68 padding) for coalesced I/O.

static constexpr int MPB = 128;   // matrices per block == threads per block
static constexpr int MS  = 68;    // padded matrix stride in floats (bank-conflict-free)

__global__ __launch_bounds__(128, 2)
void nslayer_kernel(const float* __restrict__ x,
                    const float* __restrict__ weight,
                    float* __restrict__ out)
{
    __shared__ float s[MPB * MS];
    const int tid = threadIdx.x;
    const size_t base = (size_t)blockIdx.x * (MPB * 64);

    // ---- coalesced load: block's 32KB chunk -> padded smem ----
    const float4* gin = reinterpret_cast<const float4*>(x + base);
#pragma unroll
    for (int k = 0; k < 16; k++) {
        int l4 = tid + k * 128;          // float4 index in chunk
        float4 v = gin[l4];
        int l = l4 << 2;                 // float index
        int m = l >> 6;                  // matrix within block
        int w = l & 63;                  // offset within matrix
        *reinterpret_cast<float4*>(&s[m * MS + w]) = v;
    }
    __syncthreads();

    // ---- read my matrix into Y (= X initially) ----
    float Y[8][8];
#pragma unroll
    for (int r = 0; r < 8; r++) {
        float4 a = *reinterpret_cast<const float4*>(&s[tid * MS + r * 8]);
        float4 b = *reinterpret_cast<const float4*>(&s[tid * MS + r * 8 + 4]);
        Y[r][0] = a.x; Y[r][1] = a.y; Y[r][2] = a.z; Y[r][3] = a.w;
        Y[r][4] = b.x; Y[r][5] = b.y; Y[r][6] = b.z; Y[r][7] = b.w;
    }

    // ---- A = I - Y Y^T  (symmetric: compute lower triangle, mirror) ----
    float A[8][8];
#pragma unroll
    for (int r = 0; r < 8; r++) {
#pragma unroll
        for (int c = 0; c <= r; c++) {
            float d = 0.0f;
#pragma unroll
            for (int k = 0; k < 8; k++) d = fmaf(Y[r][k], Y[c][k], d);
            float v = ((r == c) ? 1.0f : 0.0f) - d;
            A[r][c] = v;
            A[c][r] = v;
        }
    }

    // ---- Acc = (w7 + 1) * X ----
    const float w7p1 = __ldg(&weight[7]) + 1.0f;
    float Acc[8][8];
#pragma unroll
    for (int r = 0; r < 8; r++)
#pragma unroll
        for (int c = 0; c < 8; c++) Acc[r][c] = w7p1 * Y[r][c];

    // ---- Y <- A*Y seven times; Acc += w[i] * Y ----
    // Column c of the new Y depends only on column c of the old Y, so the
    // update is done in place column-by-column with an 8-reg temp.
    for (int i = 0; i < 7; i++) {
        const float wi = __ldg(&weight[i]);
#pragma unroll
        for (int c = 0; c < 8; c++) {
            float t[8];
#pragma unroll
            for (int r = 0; r < 8; r++) {
                float d = 0.0f;
#pragma unroll
                for (int k = 0; k < 8; k++) d = fmaf(A[r][k], Y[k][c], d);
                t[r] = d;
            }
#pragma unroll
            for (int r = 0; r < 8; r++) {
                Y[r][c] = t[r];
                Acc[r][c] = fmaf(wi, t[r], Acc[r][c]);
            }
        }
    }

    // ---- write result back to my smem region (no cross-thread hazard) ----
#pragma unroll
    for (int r = 0; r < 8; r++) {
        float4 a = make_float4(Acc[r][0], Acc[r][1], Acc[r][2], Acc[r][3]);
        float4 b = make_float4(Acc[r][4], Acc[r][5], Acc[r][6], Acc[r][7]);
        *reinterpret_cast<float4*>(&s[tid * MS + r * 8])     = a;
        *reinterpret_cast<float4*>(&s[tid * MS + r * 8 + 4]) = b;
    }
    __syncthreads();

    // ---- coalesced store: padded smem -> block's 32KB output chunk ----
    float4* gout = reinterpret_cast<float4*>(out + base);
#pragma unroll
    for (int k = 0; k < 16; k++) {
        int l4 = tid + k * 128;
        int l = l4 << 2;
        int m = l >> 6;
        int w = l & 63;
        gout[l4] = *reinterpret_cast<const float4*>(&s[m * MS + w]);
    }
}

extern "C" void kernel_launch(void* const* d_in, const int* in_sizes, int n_in,
                              void* d_out, int out_size) {
    const float* x = (const float*)d_in[0];
    const float* w = (const float*)d_in[1];
    float* out = (float*)d_out;
    int nmat = in_sizes[0] / 64;          // 262144
    int blocks = nmat / MPB;              // 2048 (exact)
    nslayer_kernel<<<blocks, MPB>>>(x, w, out);
}

// round 2
// speedup vs baseline: 1.3695x; 1.3695x over previous
#include <cuda_runtime.h>

// NSLayer: out = X + (w0*A + ... + w6*A^7 + w7*I) @ X,  A = I - X X^T
// 262144 independent 8x8 fp32 matrices. One thread per matrix, register
// resident, using packed fma.rn.f32x2 (SASS FFMA2) to halve fma-pipe work.
//
// Layout: all 8x8 state held as row-major adjacent float pairs (b64 regs).
//   Y2[k][cp]  = {Y[k][2cp], Y[k][2cp+1]}   (pairs along columns)
//   same registers viewed as pairs along k for the Gram dot products.
//   A2[tri] = {v, v} broadcast-packed lower triangle of symmetric A.

static constexpr int MPB = 128;   // matrices per block == threads per block
static constexpr int MS  = 68;    // padded matrix stride in floats

typedef unsigned long long u64;

__device__ __forceinline__ u64 pack2(float lo, float hi) {
    u64 r; asm("mov.b64 %0, {%1, %2};" : "=l"(r) : "f"(lo), "f"(hi)); return r;
}
__device__ __forceinline__ void unpack2(u64 v, float& lo, float& hi) {
    asm("mov.b64 {%0, %1}, %2;" : "=f"(lo), "=f"(hi) : "l"(v));
}
__device__ __forceinline__ u64 fma2(u64 a, u64 b, u64 c) {
    u64 d; asm("fma.rn.f32x2 %0, %1, %2, %3;" : "=l"(d) : "l"(a), "l"(b), "l"(c)); return d;
}
__device__ __forceinline__ u64 mul2(u64 a, u64 b) {
    u64 d; asm("mul.rn.f32x2 %0, %1, %2;" : "=l"(d) : "l"(a), "l"(b)); return d;
}

#define TRI(r, k) ((r) >= (k) ? ((r) * ((r) + 1) / 2 + (k)) : ((k) * ((k) + 1) / 2 + (r)))

__global__ __launch_bounds__(128, 2)
void nslayer_kernel(const float* __restrict__ x,
                    const float* __restrict__ weight,
                    float* __restrict__ out)
{
    __shared__ float s[MPB * MS];
    const int tid = threadIdx.x;
    const size_t base = (size_t)blockIdx.x * (MPB * 64);

    // ---- coalesced load: block's 32KB chunk -> padded smem ----
    const float4* gin = reinterpret_cast<const float4*>(x + base);
#pragma unroll
    for (int k = 0; k < 16; k++) {
        int l4 = tid + k * 128;
        float4 v = gin[l4];
        int l = l4 << 2;
        int m = l >> 6;
        int w = l & 63;
        *reinterpret_cast<float4*>(&s[m * MS + w]) = v;
    }
    __syncthreads();

    // ---- read my matrix as packed pairs (LDS.128, same banks as before) ----
    u64 Y2[8][4];
#pragma unroll
    for (int r = 0; r < 8; r++) {
        ulonglong2 p0 = *reinterpret_cast<const ulonglong2*>(&s[tid * MS + r * 8]);
        ulonglong2 p1 = *reinterpret_cast<const ulonglong2*>(&s[tid * MS + r * 8 + 4]);
        Y2[r][0] = p0.x; Y2[r][1] = p0.y; Y2[r][2] = p1.x; Y2[r][3] = p1.y;
    }

    // ---- A = I - Y Y^T : packed dot over k, broadcast-packed lower triangle ----
    u64 A2[36];
#pragma unroll
    for (int r = 0; r < 8; r++) {
#pragma unroll
        for (int c = 0; c <= r; c++) {
            u64 d2 = mul2(Y2[r][0], Y2[c][0]);
#pragma unroll
            for (int kp = 1; kp < 4; kp++) d2 = fma2(Y2[r][kp], Y2[c][kp], d2);
            float lo, hi; unpack2(d2, lo, hi);
            float v = ((r == c) ? 1.0f : 0.0f) - (lo + hi);
            A2[TRI(r, c)] = pack2(v, v);
        }
    }

    // ---- Acc = (w7 + 1) * X ----
    const float w7p1 = __ldg(&weight[7]) + 1.0f;
    const u64 w7p1x2 = pack2(w7p1, w7p1);
    u64 Acc2[8][4];
#pragma unroll
    for (int r = 0; r < 8; r++)
#pragma unroll
        for (int cp = 0; cp < 4; cp++) Acc2[r][cp] = mul2(w7p1x2, Y2[r][cp]);

    // ---- Y <- A*Y seven times (in place, column-pair by column-pair);
    //      Acc += w[i] * Y ----
    for (int i = 0; i < 7; i++) {
        const float wi = __ldg(&weight[i]);
        const u64 wi2 = pack2(wi, wi);
#pragma unroll
        for (int cp = 0; cp < 4; cp++) {
            u64 t2[8];
#pragma unroll
            for (int r = 0; r < 8; r++) {
                u64 d2 = mul2(A2[TRI(r, 0)], Y2[0][cp]);
#pragma unroll
                for (int k = 1; k < 8; k++)
                    d2 = fma2(A2[TRI(r, k)], Y2[k][cp], d2);
                t2[r] = d2;
            }
#pragma unroll
            for (int r = 0; r < 8; r++) {
                Y2[r][cp] = t2[r];
                Acc2[r][cp] = fma2(wi2, t2[r], Acc2[r][cp]);
            }
        }
    }

    // ---- write result to my smem region ----
#pragma unroll
    for (int r = 0; r < 8; r++) {
        ulonglong2 p0, p1;
        p0.x = Acc2[r][0]; p0.y = Acc2[r][1];
        p1.x = Acc2[r][2]; p1.y = Acc2[r][3];
        *reinterpret_cast<ulonglong2*>(&s[tid * MS + r * 8])     = p0;
        *reinterpret_cast<ulonglong2*>(&s[tid * MS + r * 8 + 4]) = p1;
    }
    __syncthreads();

    // ---- coalesced store: padded smem -> block's 32KB output chunk ----
    float4* gout = reinterpret_cast<float4*>(out + base);
#pragma unroll
    for (int k = 0; k < 16; k++) {
        int l4 = tid + k * 128;
        int l = l4 << 2;
        int m = l >> 6;
        int w = l & 63;
        gout[l4] = *reinterpret_cast<const float4*>(&s[m * MS + w]);
    }
}

extern "C" void kernel_launch(void* const* d_in, const int* in_sizes, int n_in,
                              void* d_out, int out_size) {
    const float* x = (const float*)d_in[0];
    const float* w = (const float*)d_in[1];
    float* out = (float*)d_out;
    int nmat = in_sizes[0] / 64;          // 262144
    int blocks = nmat / MPB;              // 2048 (exact)
    nslayer_kernel<<<blocks, MPB>>>(x, w, out);
}

// round 3
// speedup vs baseline: 1.4358x; 1.0484x over previous
#include <cuda_runtime.h>

// NSLayer: out = X + (w0*A + ... + w6*A^7 + w7*I) @ X,  A = I - X X^T
// 262144 independent 8x8 fp32 matrices. TWO threads per matrix (column split:
// thread h owns columns 4h..4h+3). Power iterations Y <- A*Y are column-local
// -> no communication; only the Gram matrix needs one 36-value shfl.bfly
// reduction. All math in packed fma.rn.f32x2 (SASS FFMA2).

static constexpr int MPB = 64;    // matrices per block
static constexpr int TPB = 128;   // threads per block (2 per matrix)
static constexpr int PL  = 130;   // smem plane stride in float4 (pad 128->130)

typedef unsigned long long u64;

__device__ __forceinline__ u64 pack2(float lo, float hi) {
    u64 r; asm("mov.b64 %0, {%1, %2};" : "=l"(r) : "f"(lo), "f"(hi)); return r;
}
__device__ __forceinline__ void unpack2(u64 v, float& lo, float& hi) {
    asm("mov.b64 {%0, %1}, %2;" : "=f"(lo), "=f"(hi) : "l"(v));
}
__device__ __forceinline__ u64 fma2(u64 a, u64 b, u64 c) {
    u64 d; asm("fma.rn.f32x2 %0, %1, %2, %3;" : "=l"(d) : "l"(a), "l"(b), "l"(c)); return d;
}
__device__ __forceinline__ u64 mul2(u64 a, u64 b) {
    u64 d; asm("mul.rn.f32x2 %0, %1, %2;" : "=l"(d) : "l"(a), "l"(b)); return d;
}

#define TRI(r, k) ((r) >= (k) ? ((r) * ((r) + 1) / 2 + (k)) : ((k) * ((k) + 1) / 2 + (r)))

__global__ __launch_bounds__(TPB, 3)
void nslayer_kernel(const float* __restrict__ x,
                    const float* __restrict__ weight,
                    float* __restrict__ out)
{
    // 8 planes; plane r holds, at float4 slot (m*2+h), row r cols 4h..4h+3 of
    // matrix m. Thread t = m*2+h reads/writes slot t of every plane.
    __shared__ float4 s4[8 * PL];
    const int tid = threadIdx.x;
    const size_t base4 = (size_t)blockIdx.x * (MPB * 16);

    // ---- coalesced load: block's 16KB chunk -> planar smem ----
    const float4* gin = reinterpret_cast<const float4*>(x) + base4;
#pragma unroll
    for (int k = 0; k < 8; k++) {
        int l4 = tid + k * TPB;
        int m = l4 >> 4, r = (l4 >> 1) & 7, q = l4 & 1;
        s4[r * PL + m * 2 + q] = gin[l4];
    }
    __syncthreads();

    // ---- my half: all 8 rows x my 4 columns, as 2 packed pairs per row ----
    u64 Y2[8][2];
#pragma unroll
    for (int r = 0; r < 8; r++) {
        ulonglong2 p = *reinterpret_cast<const ulonglong2*>(&s4[r * PL + tid]);
        Y2[r][0] = p.x; Y2[r][1] = p.y;
    }

    // ---- A = I - Y Y^T : partial dot over my 4 columns, bfly reduce with
    //      partner lane (tid^1), broadcast-pack lower triangle ----
    u64 A2[36];
#pragma unroll
    for (int r = 0; r < 8; r++) {
#pragma unroll
        for (int c = 0; c <= r; c++) {
            u64 d2 = mul2(Y2[r][0], Y2[c][0]);
            d2 = fma2(Y2[r][1], Y2[c][1], d2);
            float lo, hi; unpack2(d2, lo, hi);
            float p = lo + hi;
            p += __shfl_xor_sync(0xffffffffu, p, 1);
            float v = ((r == c) ? 1.0f : 0.0f) - p;
            A2[TRI(r, c)] = pack2(v, v);
        }
    }

    // ---- Acc = (w7 + 1) * X  (my columns) ----
    const float w7p1 = __ldg(&weight[7]) + 1.0f;
    const u64 w7p1x2 = pack2(w7p1, w7p1);
    u64 Acc2[8][2];
#pragma unroll
    for (int r = 0; r < 8; r++) {
        Acc2[r][0] = mul2(w7p1x2, Y2[r][0]);
        Acc2[r][1] = mul2(w7p1x2, Y2[r][1]);
    }

    // ---- Y <- A*Y seven times (column-local, no comm); Acc += w[i]*Y ----
    for (int i = 0; i < 7; i++) {
        const float wi = __ldg(&weight[i]);
        const u64 wi2 = pack2(wi, wi);
#pragma unroll
        for (int cp = 0; cp < 2; cp++) {
            u64 t2[8];
#pragma unroll
            for (int r = 0; r < 8; r++) {
                u64 d2 = mul2(A2[TRI(r, 0)], Y2[0][cp]);
#pragma unroll
                for (int k = 1; k < 8; k++)
                    d2 = fma2(A2[TRI(r, k)], Y2[k][cp], d2);
                t2[r] = d2;
            }
#pragma unroll
            for (int r = 0; r < 8; r++) {
                Y2[r][cp] = t2[r];
                Acc2[r][cp] = fma2(wi2, t2[r], Acc2[r][cp]);
            }
        }
    }

    // ---- write my half back to my smem slots (self-owned, no hazard) ----
#pragma unroll
    for (int r = 0; r < 8; r++) {
        ulonglong2 p; p.x = Acc2[r][0]; p.y = Acc2[r][1];
        *reinterpret_cast<ulonglong2*>(&s4[r * PL + tid]) = p;
    }
    __syncthreads();

    // ---- coalesced store: planar smem -> block's output chunk ----
    float4* gout = reinterpret_cast<float4*>(out) + base4;
#pragma unroll
    for (int k = 0; k < 8; k++) {
        int l4 = tid + k * TPB;
        int m = l4 >> 4, r = (l4 >> 1) & 7, q = l4 & 1;
        gout[l4] = s4[r * PL + m * 2 + q];
    }
}

extern "C" void kernel_launch(void* const* d_in, const int* in_sizes, int n_in,
                              void* d_out, int out_size) {
    const float* x = (const float*)d_in[0];
    const float* w = (const float*)d_in[1];
    float* out = (float*)d_out;
    int nmat = in_sizes[0] / 64;          // 262144
    int blocks = nmat / MPB;              // 4096 (exact)
    nslayer_kernel<<<blocks, TPB>>>(x, w, out);
}